// round 2
// baseline (speedup 1.0000x reference)
#include <cuda_runtime.h>

// Problem constants
#define Bn 512
#define Dn 768
#define Ln 128
#define Rn 128
#define BD (Bn * Dn)        // 393216 floats per "l" slab
#define KC 32               // K chunk
#define TLD 132             // tile leading dim (padded, keeps float4 alignment)
#define EPS 1e-4f           // near-tie window for fp64 refinement

// Output offsets (floats), in reference tuple order
#define LD_OFF 0ull
#define RD_OFF 50331648ull
#define LM_OFF 100663296ull
#define RM_OFF 100728832ull
#define LS_OFF 100794368ull
#define RS_OFF 100859904ull

// Scratch: inverse norms over batch axis (fp32 for GEMM, fp64 for refinement)
__device__ float  g_invL[Ln * Dn];
__device__ float  g_invR[Rn * Dn];
__device__ double g_inv64L[Ln * Dn];
__device__ double g_inv64R[Rn * Dn];

// ---------------------------------------------------------------------------
// Kernel 1: inv_n[l,d] = 1/sqrt(sum_b x[l,b,d]^2), fp64 accumulation
// ---------------------------------------------------------------------------
__global__ __launch_bounds__(256) void norms_kernel(const float* __restrict__ left,
                                                    const float* __restrict__ right) {
    int gid = blockIdx.x * blockDim.x + threadIdx.x;
    const int LD = Ln * Dn;
    const float* src;
    float* dst32;
    double* dst64;
    int idx;
    if (gid < LD) { src = left;  dst32 = g_invL; dst64 = g_inv64L; idx = gid; }
    else          { src = right; dst32 = g_invR; dst64 = g_inv64R; idx = gid - LD; }
    int l = idx / Dn;
    int d = idx - l * Dn;
    const float* p = src + (size_t)l * BD + d;
    double acc = 0.0;
#pragma unroll 8
    for (int b = 0; b < Bn; b++) {
        double v = (double)p[(size_t)b * Dn];
        acc += v * v;
    }
    double inv = 1.0 / sqrt(acc);
    dst64[idx] = inv;
    dst32[idx] = (float)inv;
}

// ---------------------------------------------------------------------------
// Warp-collective fp64 dot of normalized vectors: sum_d L[l,b,d]R[r,b,d]/(nl nr)
// All 32 lanes participate; all return the same total.
// ---------------------------------------------------------------------------
__device__ __forceinline__ double dot64(const float* __restrict__ left,
                                        const float* __restrict__ right,
                                        int l, int r, int b) {
    const int lane = threadIdx.x & 31;
    const float*  lp = left  + (size_t)l * BD + (size_t)b * Dn;
    const float*  rp = right + (size_t)r * BD + (size_t)b * Dn;
    const double* il = g_inv64L + l * Dn;
    const double* ir = g_inv64R + r * Dn;
    double acc = 0.0;
    for (int d = lane; d < Dn; d += 32)
        acc += (double)lp[d] * (double)rp[d] * il[d] * ir[d];
#pragma unroll
    for (int off = 16; off; off >>= 1)
        acc += __shfl_xor_sync(0xffffffffu, acc, off);
    return acc;
}

// ---------------------------------------------------------------------------
// Kernel 2: one CTA per batch b.
// ---------------------------------------------------------------------------
__global__ __launch_bounds__(256) void main_kernel(const float* __restrict__ left,
                                                   const int*   __restrict__ llen,
                                                   const float* __restrict__ right,
                                                   const int*   __restrict__ rlen,
                                                   float*       __restrict__ out) {
    const int b   = blockIdx.x;
    const int tid = threadIdx.x;
    const int tx  = tid & 15;   // 0..15  (column group)
    const int ty  = tid >> 4;   // 0..15  (row group)

    __shared__ float lm[Ln];
    __shared__ float rm[Rn];
    __shared__ int   lidx[Ln];
    __shared__ int   ridx[Rn];

    extern __shared__ float smem[];          // 128*129 floats = 66048 B
    float* As  = smem;                       // [KC][TLD]
    float* Bs  = smem + KC * TLD;            // [KC][TLD]
    float* att = smem;                       // aliases tiles after GEMM

    // -------- Phase 1: masks --------
    {
        const int ll = llen[b];
        const int rl = rlen[b];
        if (tid < 128) {
            float lmv = (tid < ll) ? 1.0f : 0.0f;
            float rmv = (tid < rl) ? 1.0f : 0.0f;
            lm[tid] = lmv;
            rm[tid] = rmv;
            out[LM_OFF + (size_t)b * Ln + tid] = lmv;
            out[RM_OFF + (size_t)b * Rn + tid] = rmv;
        }
    }
    __syncthreads();

    // -------- Phase 2: GEMM --------
    float acc[8][8];
#pragma unroll
    for (int i = 0; i < 8; i++)
#pragma unroll
        for (int j = 0; j < 8; j++) acc[i][j] = 0.f;

    const float* lbase = left  + (size_t)b * Dn;
    const float* rbase = right + (size_t)b * Dn;

    for (int k0 = 0; k0 < Dn; k0 += KC) {
#pragma unroll
        for (int j = 0; j < 4; j++) {
            int i   = tid + 256 * j;        // 0..1023 -> 128 rows x 8 float4
            int row = i >> 3;
            int dq  = (i & 7) << 2;
            int d   = k0 + dq;

            float4 va = *(const float4*)(lbase + (size_t)row * BD + d);
            float4 na = *(const float4*)(g_invL + row * Dn + d);
            As[(dq + 0) * TLD + row] = va.x * na.x;
            As[(dq + 1) * TLD + row] = va.y * na.y;
            As[(dq + 2) * TLD + row] = va.z * na.z;
            As[(dq + 3) * TLD + row] = va.w * na.w;

            float4 vb = *(const float4*)(rbase + (size_t)row * BD + d);
            float4 nb = *(const float4*)(g_invR + row * Dn + d);
            Bs[(dq + 0) * TLD + row] = vb.x * nb.x;
            Bs[(dq + 1) * TLD + row] = vb.y * nb.y;
            Bs[(dq + 2) * TLD + row] = vb.z * nb.z;
            Bs[(dq + 3) * TLD + row] = vb.w * nb.w;
        }
        __syncthreads();

        const float* ap = As + ty * 8;
        const float* bp = Bs + tx * 8;
#pragma unroll
        for (int kk = 0; kk < KC; kk++) {
            float4 a0 = *(const float4*)(ap + kk * TLD);
            float4 a1 = *(const float4*)(ap + kk * TLD + 4);
            float4 b0 = *(const float4*)(bp + kk * TLD);
            float4 b1 = *(const float4*)(bp + kk * TLD + 4);
            float a[8]  = {a0.x, a0.y, a0.z, a0.w, a1.x, a1.y, a1.z, a1.w};
            float bb[8] = {b0.x, b0.y, b0.z, b0.w, b1.x, b1.y, b1.z, b1.w};
#pragma unroll
            for (int i = 0; i < 8; i++)
#pragma unroll
                for (int j = 0; j < 8; j++)
                    acc[i][j] = fmaf(a[i], bb[j], acc[i][j]);
        }
        __syncthreads();
    }

    // -------- Phase 3: masked attention to smem --------
#pragma unroll
    for (int i = 0; i < 8; i++) {
        int row = ty * 8 + i;
        float lmv = lm[row];
#pragma unroll
        for (int j = 0; j < 8; j++) {
            int col = tx * 8 + j;
            att[row * 129 + col] = acc[i][j] * lmv * rm[col];
        }
    }
    __syncthreads();

    // -------- Phase 4: reductions with fp64 near-tie refinement --------
    const int warp = tid >> 5;
    const int lane = tid & 31;

    // Rows: left_sim / l_idx  (max over r)
    for (int r8 = 0; r8 < 16; r8++) {
        int row = warp * 16 + r8;
        float best = att[row * 129 + lane];
        int   bi   = lane;
#pragma unroll
        for (int m = 1; m < 4; m++) {
            float v = att[row * 129 + lane + 32 * m];
            if (v > best) { best = v; bi = lane + 32 * m; }
        }
#pragma unroll
        for (int off = 16; off; off >>= 1) {
            float ov = __shfl_xor_sync(0xffffffffu, best, off);
            int   oi = __shfl_xor_sync(0xffffffffu, bi,   off);
            if (ov > best || (ov == best && oi < bi)) { best = ov; bi = oi; }
        }
        // all lanes now agree on (best, bi)
        float thr = best - EPS;
        int cnt = 0;
        {
#pragma unroll
            for (int m = 0; m < 4; m++) {
                float v = att[row * 129 + m * 32 + lane];
                cnt += __popc(__ballot_sync(0xffffffffu, v >= thr));
            }
        }
        int fi = bi;
        if (cnt >= 2) {
            // refine: exact fp64 comparison of near-tied candidates.
            // If best == 0 (mask-dominated row), the base reduction already found
            // the first exact-zero index; only nonzero near-zero dots can beat it.
            bool zmode = (best == 0.0f);
            double bbest;
            int    bbi;
            if (zmode) { bbest = 0.0; bbi = bi; }
            else       { bbest = -1e300; bbi = -1; }
#pragma unroll
            for (int m = 0; m < 4; m++) {
                float v = att[row * 129 + m * 32 + lane];
                bool near = (v >= thr) && (!zmode || v != 0.0f);
                unsigned bal = __ballot_sync(0xffffffffu, near);
                while (bal) {
                    int ln = __ffs(bal) - 1;
                    bal &= bal - 1;
                    int cand = m * 32 + ln;
                    bool masked = (lm[row] == 0.0f) || (rm[cand] == 0.0f);
                    double val = masked ? 0.0 : dot64(left, right, row, cand, b);
                    if (val > bbest || (val == bbest && cand < bbi)) { bbest = val; bbi = cand; }
                }
            }
            fi = bbi;
        }
        if (lane == 0) {
            out[LS_OFF + (size_t)row * Bn + b] = att[row * 129 + fi];
            lidx[row] = fi;
        }
    }

    // Columns: right_sim / r_idx  (max over l)
    for (int c8 = 0; c8 < 16; c8++) {
        int col = warp * 16 + c8;
        float best = att[lane * 129 + col];
        int   bi   = lane;
#pragma unroll
        for (int m = 1; m < 4; m++) {
            float v = att[(lane + 32 * m) * 129 + col];
            if (v > best) { best = v; bi = lane + 32 * m; }
        }
#pragma unroll
        for (int off = 16; off; off >>= 1) {
            float ov = __shfl_xor_sync(0xffffffffu, best, off);
            int   oi = __shfl_xor_sync(0xffffffffu, bi,   off);
            if (ov > best || (ov == best && oi < bi)) { best = ov; bi = oi; }
        }
        float thr = best - EPS;
        int cnt = 0;
        {
#pragma unroll
            for (int m = 0; m < 4; m++) {
                float v = att[(m * 32 + lane) * 129 + col];
                cnt += __popc(__ballot_sync(0xffffffffu, v >= thr));
            }
        }
        int fi = bi;
        if (cnt >= 2) {
            bool zmode = (best == 0.0f);
            double bbest;
            int    bbi;
            if (zmode) { bbest = 0.0; bbi = bi; }
            else       { bbest = -1e300; bbi = -1; }
#pragma unroll
            for (int m = 0; m < 4; m++) {
                float v = att[(m * 32 + lane) * 129 + col];
                bool near = (v >= thr) && (!zmode || v != 0.0f);
                unsigned bal = __ballot_sync(0xffffffffu, near);
                while (bal) {
                    int ln = __ffs(bal) - 1;
                    bal &= bal - 1;
                    int cand = m * 32 + ln;
                    bool masked = (lm[cand] == 0.0f) || (rm[col] == 0.0f);
                    double val = masked ? 0.0 : dot64(left, right, cand, col, b);
                    if (val > bbest || (val == bbest && cand < bbi)) { bbest = val; bbi = cand; }
                }
            }
            fi = bbi;
        }
        if (lane == 0) {
            out[RS_OFF + (size_t)col * Bn + b] = att[fi * 129 + col];
            ridx[col] = fi;
        }
    }
    __syncthreads();

    // -------- Phase 5: difference gathers --------
    const float4* l4 = (const float4*)left;
    const float4* r4 = (const float4*)right;
    float4* old4 = (float4*)(out + LD_OFF);
    float4* ord4 = (float4*)(out + RD_OFF);
    const int ROW4 = Dn / 4;        // 192 float4 per (l,b) row
    const int BD4  = BD / 4;        // 98304

    for (int i = tid; i < Ln * ROW4; i += 256) {
        int row = i / ROW4;
        int dq  = i - row * ROW4;
        size_t o = (size_t)row * BD4 + (size_t)b * ROW4 + dq;
        float4 res;
        if (lm[row] != 0.f) {
            float4 a = l4[o];
            float4 c = r4[(size_t)lidx[row] * BD4 + (size_t)b * ROW4 + dq];
            res = make_float4(a.x - c.x, a.y - c.y, a.z - c.z, a.w - c.w);
        } else {
            res = make_float4(0.f, 0.f, 0.f, 0.f);
        }
        old4[o] = res;
    }

    for (int i = tid; i < Rn * ROW4; i += 256) {
        int row = i / ROW4;
        int dq  = i - row * ROW4;
        size_t o = (size_t)row * BD4 + (size_t)b * ROW4 + dq;
        float4 res;
        if (rm[row] != 0.f) {
            float4 a = r4[o];
            float4 c = l4[(size_t)ridx[row] * BD4 + (size_t)b * ROW4 + dq];
            res = make_float4(a.x - c.x, a.y - c.y, a.z - c.z, a.w - c.w);
        } else {
            res = make_float4(0.f, 0.f, 0.f, 0.f);
        }
        ord4[o] = res;
    }
}

// ---------------------------------------------------------------------------
extern "C" void kernel_launch(void* const* d_in, const int* in_sizes, int n_in,
                              void* d_out, int out_size) {
    (void)in_sizes; (void)n_in; (void)out_size;
    const float* left  = (const float*)d_in[0];
    const int*   llen  = (const int*)d_in[1];
    const float* right = (const float*)d_in[2];
    const int*   rlen  = (const int*)d_in[3];
    float* out = (float*)d_out;

    const int SMEM = 128 * 129 * sizeof(float);  // 66048 B
    cudaFuncSetAttribute(main_kernel, cudaFuncAttributeMaxDynamicSharedMemorySize, SMEM);

    norms_kernel<<<(2 * Ln * Dn) / 256, 256>>>(left, right);
    main_kernel<<<Bn, 256, SMEM>>>(left, llen, right, rlen, out);
}